// round 14
// baseline (speedup 1.0000x reference)
#include <cuda_runtime.h>
#include <cuda_fp16.h>
#include <cstdint>

#define DI __device__ __forceinline__

constexpr int SEQ = 2048, HIDN = 1024, NHD = 16, ITR = 4096, HD = 256;

// ---------------- scratch (device globals; allocation-free) ----------------
__device__ __align__(16) __half g_xh [SEQ * HIDN];
__device__ __align__(16) __half g_wg [ITR * HIDN];
__device__ __align__(16) __half g_wu [ITR * HIDN];
__device__ __align__(16) __half g_wd [HIDN * ITR];
__device__ __align__(16) __half g_wq [NHD * HD * HD];
__device__ __align__(16) __half g_wk [NHD * HD * HD];
__device__ __align__(16) __half g_w1 [HD * 4 * HD];
__device__ __align__(16) __half g_w2 [HD * HD];
__device__ __align__(16) __half g_adjh[(size_t)NHD * SEQ * SEQ];
__device__ __align__(16) __half g_h  [SEQ * ITR];
__device__ __align__(16) __half g_hT [NHD * HD * SEQ];
__device__ __align__(16) __half g_q  [NHD * SEQ * HD];
__device__ __align__(16) __half g_k2 [NHD * SEQ * HD];
__device__ __align__(16) __half g_ph [(size_t)NHD * SEQ * SEQ];
__device__ float                g_rs [NHD * SEQ];
__device__ __align__(16) __half g_cb [(size_t)NHD * SEQ * 4 * HD];
__device__ __align__(16) __half g_t  [NHD * SEQ * HD];
__device__ __align__(16) __half g_gin[SEQ * ITR];

// ---------------- MUFU-free math ----------------
DI float exp_nm(float x){
  float t = fminf(fmaxf(x * 1.44269504f, -126.f), 126.f);
  float n = rintf(t);
  float y = (t - n) * 0.693147181f;
  float p = 1.f + y*(1.f + y*(0.5f + y*(0.166666667f + y*(0.0416666667f +
            y*(0.00833333333f + y*0.00138888889f)))));
  return p * __int_as_float(((int)n + 127) << 23);
}
DI float recip_nm(float d){
  float r = __int_as_float(0x7EF311C3u - __float_as_uint(d));
  r = r * (2.f - d*r); r = r * (2.f - d*r); r = r * (2.f - d*r);
  return r;
}
DI float silu_nm(float v){ return v * recip_nm(1.f + exp_nm(-v)); }

DI void mma16(float c[4], const uint32_t a[4], const uint32_t b[2]){
  asm volatile("mma.sync.aligned.m16n8k16.row.col.f32.f16.f16.f32 "
    "{%0,%1,%2,%3},{%4,%5,%6,%7},{%8,%9},{%0,%1,%2,%3};\n"
    : "+f"(c[0]),"+f"(c[1]),"+f"(c[2]),"+f"(c[3])
    : "r"(a[0]),"r"(a[1]),"r"(a[2]),"r"(a[3]),"r"(b[0]),"r"(b[1]));
}
DI void ldsm4(uint32_t d[4], uint32_t addr){
  asm volatile("ldmatrix.sync.aligned.m8n8.x4.shared.b16 {%0,%1,%2,%3}, [%4];"
    : "=r"(d[0]),"=r"(d[1]),"=r"(d[2]),"=r"(d[3]) : "r"(addr));
}
DI void ldsm2(uint32_t d[2], uint32_t addr){
  asm volatile("ldmatrix.sync.aligned.m8n8.x2.shared.b16 {%0,%1}, [%2];"
    : "=r"(d[0]),"=r"(d[1]) : "r"(addr));
}
DI uint32_t cvta_s(const void* p){ return (uint32_t)__cvta_generic_to_shared(p); }
DI void cpa16(uint32_t dst, const void* src){
  asm volatile("cp.async.cg.shared.global [%0], [%1], 16;" :: "r"(dst), "l"(src));
}
DI void cpa_commit(){ asm volatile("cp.async.commit_group;" ::: "memory"); }
template<int N> DI void cpa_wait(){ asm volatile("cp.async.wait_group %0;" :: "n"(N) : "memory"); }

enum { E_RAW=0, E_SWIGLU=1, E_PEXP=2, E_SCALEH=3, E_SILU=4, E_RSCALE=5 };

struct GArg {
  const void* A; long long sA; int lda;
  const void* B; long long sB; int ldb;
  void*       C; long long sC; int ldc;
  const void* X; long long sX; int ldx;
  const float* pvec;
  const float* rvec;
  float*       rout;
  int K;
};

template<int EPI, typename CT>
DI void st2(const GArg& g, int b, long long rg, long long cg, float v0, float v1){
  float o0, o1;
  if (EPI == E_RAW){ o0 = v0; o1 = v1; }
  else if (EPI == E_SWIGLU){
    __half2 u = *(const __half2*)((const __half*)g.X + rg*(long long)g.ldx + cg);
    o0 = silu_nm(v0) * __half2float(u.x); o1 = silu_nm(v1) * __half2float(u.y);
  } else if (EPI == E_PEXP){
    __half2 a2 = *(const __half2*)((const __half*)g.X + (long long)b*g.sX + rg*(long long)g.ldx + cg);
    o0 = exp_nm(v0*0.0625f) * (__half2float(a2.x) + 1e-9f);
    o1 = exp_nm(v1*0.0625f) * (__half2float(a2.y) + 1e-9f);
    float s = o0 + o1;
    s += __shfl_xor_sync(0xffffffffu, s, 1);
    s += __shfl_xor_sync(0xffffffffu, s, 2);
    if ((threadIdx.x & 3) == 0) atomicAdd(g.rout + (long long)b*SEQ + rg, s);
  } else if (EPI == E_SCALEH){ float s = g.pvec[b]; o0 = v0*s; o1 = v1*s; }
  else if (EPI == E_RSCALE){
    float s = recip_nm(g.rvec[(long long)b*SEQ + rg]); o0 = v0*s; o1 = v1*s;
  } else { o0 = silu_nm(v0); o1 = silu_nm(v1); }
  CT* p = (CT*)g.C + (long long)b*g.sC + rg*(long long)g.ldc + cg;
  if constexpr (sizeof(CT) == 2) *(__half2*)p = __floats2half2_rn(o0, o1);
  else                           *(float2*)p  = make_float2(o0, o1);
}

constexpr int ROWH = 40;                       // halfs per smem row (80B)
constexpr int NST = 4;

// ============ small GEMM: 128x128 CTA, 8 warps (2x4), 64x32 warp tile ============
constexpr int TILEH_S = 128 * ROWH;
constexpr int STAGEB_S = 2 * TILEH_S * 2;      // 20480
constexpr int SMEM_S = NST * STAGEB_S;         // 81920

template<int EPI, typename CT>
__global__ void __launch_bounds__(256, 2) gemm_h(GArg g){
  extern __shared__ __half smh[];
  const int b = blockIdx.z;
  const __half* A = (const __half*)g.A + (long long)b*g.sA;
  const __half* B = (const __half*)g.B + (long long)b*g.sB;
  const int m0 = blockIdx.y * 128, n0 = blockIdx.x * 128;
  const int tid = threadIdx.x, lane = tid & 31, wid = tid >> 5;
  const int wm = wid & 1, wn = wid >> 1;
  const int ar = lane >> 2, ac = lane & 3;
  float acc[4][4][4] = {};

  const int rF = tid >> 1;
  const int cB = (tid & 1) * 32;

  const uint32_t smem0 = cvta_s(smh);
  const uint32_t aBase = smem0 + (wm*64 + (lane & 7) + ((lane >> 3) & 1)*8)*(ROWH*2)
                       + ((lane >> 4) & 1)*16;
  const uint32_t bBase = smem0 + TILEH_S*2 + (wn*32 + (lane & 7))*(ROWH*2)
                       + ((lane >> 3) & 1)*16;
  const int ktiles = g.K >> 5;

  auto issue = [&](int kt){
    if (kt < ktiles){
      int st = kt & (NST - 1);
      uint32_t ds = smem0 + st*STAGEB_S + rF*(ROWH*2) + cB;
      const char* sa = (const char*)(A + (long long)(m0 + rF)*g.lda + kt*32) + cB;
      const char* sb = (const char*)(B + (long long)(n0 + rF)*g.ldb + kt*32) + cB;
      cpa16(ds,               sa);
      cpa16(ds + 16,          sa + 16);
      cpa16(ds + TILEH_S*2,      sb);
      cpa16(ds + TILEH_S*2 + 16, sb + 16);
    }
    cpa_commit();
  };

  issue(0); issue(1); issue(2);

  for (int kt = 0; kt < ktiles; kt++){
    cpa_wait<2>();
    __syncthreads();
    issue(kt + 3);
    const uint32_t so = (uint32_t)(kt & (NST - 1)) * STAGEB_S;
    #pragma unroll
    for (int kk = 0; kk < 32; kk += 16){
      uint32_t af[4][4], bf[4][2];
      #pragma unroll
      for (int mt = 0; mt < 4; mt++)
        ldsm4(af[mt], aBase + so + mt*16*(ROWH*2) + kk*2);
      #pragma unroll
      for (int nt = 0; nt < 4; nt++)
        ldsm2(bf[nt], bBase + so + nt*8*(ROWH*2) + kk*2);
      #pragma unroll
      for (int mt = 0; mt < 4; mt++)
        #pragma unroll
        for (int nt = 0; nt < 4; nt++)
          mma16(acc[mt][nt], af[mt], bf[nt]);
    }
    __syncthreads();
  }

  #pragma unroll
  for (int mt = 0; mt < 4; mt++)
    #pragma unroll
    for (int nt = 0; nt < 4; nt++){
      long long rg = m0 + wm*64 + mt*16 + ar;
      long long cg = n0 + wn*32 + nt*8 + (ac << 1);
      st2<EPI, CT>(g, b, rg,   cg, acc[mt][nt][0], acc[mt][nt][1]);
      st2<EPI, CT>(g, b, rg+8, cg, acc[mt][nt][2], acc[mt][nt][3]);
    }
}

// ============ big GEMM: 256x256 CTA, 16 warps (4x4), 64x64 warp tile ============
constexpr int TILEH_B = 256 * ROWH;
constexpr int STAGEB_B = 2 * TILEH_B * 2;      // 40960
constexpr int SMEM_B = NST * STAGEB_B;         // 163840

template<int EPI, typename CT>
__global__ void __launch_bounds__(512, 1) gemm_b(GArg g){
  extern __shared__ __half smh[];
  const int b = blockIdx.z;
  const __half* A = (const __half*)g.A + (long long)b*g.sA;
  const __half* B = (const __half*)g.B + (long long)b*g.sB;
  const int m0 = blockIdx.y * 256, n0 = blockIdx.x * 256;
  const int tid = threadIdx.x, lane = tid & 31, wid = tid >> 5;
  const int wm = wid & 3, wn = wid >> 2;       // 4x4 warps, 64x64 each
  const int ar = lane >> 2, ac = lane & 3;
  float acc[4][8][4] = {};

  const int rF = tid >> 1;                     // 0..255
  const int cB = (tid & 1) * 32;

  const uint32_t smem0 = cvta_s(smh);
  const uint32_t aBase = smem0 + (wm*64 + (lane & 7) + ((lane >> 3) & 1)*8)*(ROWH*2)
                       + ((lane >> 4) & 1)*16;
  const uint32_t bBase = smem0 + TILEH_B*2 + (wn*64 + (lane & 7) + ((lane >> 4) & 1)*8)*(ROWH*2)
                       + ((lane >> 3) & 1)*16;
  const int ktiles = g.K >> 5;

  auto issue = [&](int kt){
    if (kt < ktiles){
      int st = kt & (NST - 1);
      uint32_t ds = smem0 + st*STAGEB_B + rF*(ROWH*2) + cB;
      const char* sa = (const char*)(A + (long long)(m0 + rF)*g.lda + kt*32) + cB;
      const char* sb = (const char*)(B + (long long)(n0 + rF)*g.ldb + kt*32) + cB;
      cpa16(ds,               sa);
      cpa16(ds + 16,          sa + 16);
      cpa16(ds + TILEH_B*2,      sb);
      cpa16(ds + TILEH_B*2 + 16, sb + 16);
    }
    cpa_commit();
  };

  issue(0); issue(1); issue(2);

  for (int kt = 0; kt < ktiles; kt++){
    cpa_wait<2>();
    __syncthreads();
    issue(kt + 3);
    const uint32_t so = (uint32_t)(kt & (NST - 1)) * STAGEB_B;
    #pragma unroll
    for (int kk = 0; kk < 32; kk += 16){
      uint32_t af[4][4], bf[8][2];
      #pragma unroll
      for (int mt = 0; mt < 4; mt++)
        ldsm4(af[mt], aBase + so + mt*16*(ROWH*2) + kk*2);
      #pragma unroll
      for (int np = 0; np < 4; np++){
        uint32_t b4[4];
        ldsm4(b4, bBase + so + np*16*(ROWH*2) + kk*2);
        bf[np*2+0][0] = b4[0]; bf[np*2+0][1] = b4[1];
        bf[np*2+1][0] = b4[2]; bf[np*2+1][1] = b4[3];
      }
      #pragma unroll
      for (int mt = 0; mt < 4; mt++)
        #pragma unroll
        for (int nt = 0; nt < 8; nt++)
          mma16(acc[mt][nt], af[mt], bf[nt]);
    }
    __syncthreads();
  }

  #pragma unroll
  for (int mt = 0; mt < 4; mt++)
    #pragma unroll
    for (int nt = 0; nt < 8; nt++){
      long long rg = m0 + wm*64 + mt*16 + ar;
      long long cg = n0 + wn*64 + nt*8 + (ac << 1);
      st2<EPI, CT>(g, b, rg,   cg, acc[mt][nt][0], acc[mt][nt][1]);
      st2<EPI, CT>(g, b, rg+8, cg, acc[mt][nt][2], acc[mt][nt][3]);
    }
}

// ---------------- batched fp32 -> fp16 converters ----------------
struct CvtJob { const float* src; __half* dst; long long n8; };

DI void cvt_body(const CvtJob& j){
  long long i = (long long)blockIdx.x * 256 + threadIdx.x;
  if (i >= j.n8) return;
  float4 a = ((const float4*)j.src)[i*2], c = ((const float4*)j.src)[i*2+1];
  __half2 h0 = __floats2half2_rn(a.x,a.y), h1 = __floats2half2_rn(a.z,a.w);
  __half2 h2 = __floats2half2_rn(c.x,c.y), h3 = __floats2half2_rn(c.z,c.w);
  ((uint4*)j.dst)[i] = make_uint4(*(uint32_t*)&h0, *(uint32_t*)&h1,
                                  *(uint32_t*)&h2, *(uint32_t*)&h3);
}
__global__ void kf2h1(CvtJob j0){ cvt_body(j0); }
__global__ void kf2hN(CvtJob j0, CvtJob j1, CvtJob j2, CvtJob j3){
  CvtJob j = (blockIdx.y==0)?j0:(blockIdx.y==1)?j1:(blockIdx.y==2)?j2:j3;
  cvt_body(j);
}
__global__ void kzero(float* p, int n){
  int i = blockIdx.x * 256 + threadIdx.x;
  if (i < n) p[i] = 0.f;
}

// ---------------- per-head transpose ----------------
__global__ void ktrans(const __half* __restrict__ h, __half* __restrict__ hT){
  __shared__ __half t[32][34];
  int hd = blockIdx.z;
  int s0 = blockIdx.y * 32, d0 = blockIdx.x * 32;
  int tx = threadIdx.x, ty = threadIdx.y;
  #pragma unroll
  for (int i = 0; i < 32; i += 8)
    t[ty+i][tx] = h[(long long)(s0+ty+i)*4096 + hd*256 + d0 + tx];
  __syncthreads();
  #pragma unroll
  for (int i = 0; i < 32; i += 8)
    hT[(long long)hd*(256*2048) + (long long)(d0+ty+i)*2048 + s0 + tx] = t[tx][ty+i];
}

// ---------------- fill comb slices 0 (orig) and 2 (max) ----------------
__global__ void kcomb(const __half* __restrict__ h, __half* __restrict__ comb,
                      const float* __restrict__ eps){
  long long i = (long long)blockIdx.x * 256 + threadIdx.x;
  int d = (int)(i & 255);
  long long sh = i >> 8;
  int s = (int)(sh & 2047);
  int hd = (int)(sh >> 11);
  float hv = __half2float(h[(long long)s * 4096 + hd * 256 + d]);
  long long base = (long long)hd * (2048 * 1024) + (long long)s * 1024 + d;
  comb[base]       = __float2half_rn((1.f + eps[hd]) * hv);
  comb[base + 512] = __float2half_rn(hv);
}

// ---------------- launch ----------------
extern "C" void kernel_launch(void* const* d_in, const int* in_sizes, int n_in,
                              void* d_out, int out_size){
  const float* x    = (const float*)d_in[0];
  const float* adj  = (const float*)d_in[1];
  const float* Wg   = (const float*)d_in[2];
  const float* Wu   = (const float*)d_in[3];
  const float* Wd   = (const float*)d_in[4];
  const float* eps  = (const float*)d_in[5];
  const float* alpha= (const float*)d_in[6];
  const float* Wq   = (const float*)d_in[7];
  const float* Wk   = (const float*)d_in[8];
  const float* W1   = (const float*)d_in[9];
  const float* W2   = (const float*)d_in[10];
  float* out = (float*)d_out;

  __half *pxh,*pwg,*pwu,*pwd,*pwq,*pwk,*pw1,*pw2,*padjh,*ph,*phT,*pq,*pk,*pph,*pcb,*pt,*pg;
  float *prs;
  cudaGetSymbolAddress((void**)&pxh,  g_xh);
  cudaGetSymbolAddress((void**)&pwg,  g_wg);
  cudaGetSymbolAddress((void**)&pwu,  g_wu);
  cudaGetSymbolAddress((void**)&pwd,  g_wd);
  cudaGetSymbolAddress((void**)&pwq,  g_wq);
  cudaGetSymbolAddress((void**)&pwk,  g_wk);
  cudaGetSymbolAddress((void**)&pw1,  g_w1);
  cudaGetSymbolAddress((void**)&pw2,  g_w2);
  cudaGetSymbolAddress((void**)&padjh,g_adjh);
  cudaGetSymbolAddress((void**)&ph,   g_h);
  cudaGetSymbolAddress((void**)&phT,  g_hT);
  cudaGetSymbolAddress((void**)&pq,   g_q);
  cudaGetSymbolAddress((void**)&pk,   g_k2);
  cudaGetSymbolAddress((void**)&pph,  g_ph);
  cudaGetSymbolAddress((void**)&prs,  g_rs);
  cudaGetSymbolAddress((void**)&pcb,  g_cb);
  cudaGetSymbolAddress((void**)&pt,   g_t);
  cudaGetSymbolAddress((void**)&pg,   g_gin);

  static cudaStream_t s1 = nullptr, s2 = nullptr;
  static cudaEvent_t ev0, evA, evT, ev4, ev8, evC, evH, evW;
  static bool init_done = false;
  if (!init_done){
    cudaFuncSetAttribute(gemm_b<E_RAW,__half>,    cudaFuncAttributeMaxDynamicSharedMemorySize, SMEM_B);
    cudaFuncSetAttribute(gemm_b<E_SWIGLU,__half>, cudaFuncAttributeMaxDynamicSharedMemorySize, SMEM_B);
    cudaFuncSetAttribute(gemm_b<E_PEXP,__half>,   cudaFuncAttributeMaxDynamicSharedMemorySize, SMEM_B);
    cudaFuncSetAttribute(gemm_b<E_SCALEH,__half>, cudaFuncAttributeMaxDynamicSharedMemorySize, SMEM_B);
    cudaFuncSetAttribute(gemm_b<E_RSCALE,__half>, cudaFuncAttributeMaxDynamicSharedMemorySize, SMEM_B);
    cudaFuncSetAttribute(gemm_b<E_SILU,__half>,   cudaFuncAttributeMaxDynamicSharedMemorySize, SMEM_B);
    cudaFuncSetAttribute(gemm_h<E_RAW,float>,     cudaFuncAttributeMaxDynamicSharedMemorySize, SMEM_S);
    cudaStreamCreateWithFlags(&s1, cudaStreamNonBlocking);
    cudaStreamCreateWithFlags(&s2, cudaStreamNonBlocking);
    cudaEventCreateWithFlags(&ev0, cudaEventDisableTiming);
    cudaEventCreateWithFlags(&evA, cudaEventDisableTiming);
    cudaEventCreateWithFlags(&evT, cudaEventDisableTiming);
    cudaEventCreateWithFlags(&ev4, cudaEventDisableTiming);
    cudaEventCreateWithFlags(&ev8, cudaEventDisableTiming);
    cudaEventCreateWithFlags(&evC, cudaEventDisableTiming);
    cudaEventCreateWithFlags(&evH, cudaEventDisableTiming);
    cudaEventCreateWithFlags(&evW, cudaEventDisableTiming);
    init_done = true;
  }
  cudaStream_t s0 = 0;
  auto J = [](const float* s, __half* d, long long n){ CvtJob j{s, d, n >> 3}; return j; };
  CvtJob jz{nullptr, nullptr, 0};

  kzero<<<NHD*SEQ/256, 256, 0, s0>>>(prs, NHD*SEQ);
  cudaEventRecord(ev0, s0);

  cudaStreamWaitEvent(s1, ev0, 0);
  kf2h1<<<dim3(32768,1), 256, 0, s1>>>(J(adj, padjh, (long long)NHD*SEQ*SEQ));
  cudaEventRecord(evH, s1);

  cudaStreamWaitEvent(s2, ev0, 0);
  kf2h1<<<dim3(512,1), 256, 0, s2>>>(J(Wk, pwk, (long long)NHD*HD*HD));
  kf2hN<<<dim3(2048,4), 256, 0, s2>>>(J(Wq, pwq, (long long)NHD*HD*HD),
                                      J(W1, pw1, (long long)HD*4*HD),
                                      J(W2, pw2, (long long)HD*HD),
                                      J(Wd, pwd, (long long)HIDN*ITR));
  cudaEventRecord(evW, s2);

  kf2hN<<<dim3(2048,3), 256, 0, s0>>>(J(x, pxh, (long long)SEQ*HIDN),
                                      J(Wu, pwu, (long long)ITR*HIDN),
                                      J(Wg, pwg, (long long)ITR*HIDN), jz);

  GArg a; a.pvec = nullptr; a.rvec = nullptr; a.rout = nullptr;
  a.X = nullptr; a.sX = 0; a.ldx = 0;

  // s0: 1) U ; 2) h (big tiles: grid 16x8)
  a.A=pxh; a.sA=0; a.lda=1024; a.B=pwu; a.sB=0; a.ldb=1024;
  a.C=pg;  a.sC=0; a.ldc=4096; a.K=1024;
  gemm_b<E_RAW,__half><<<dim3(16,8,1), 512, SMEM_B, s0>>>(a);
  a.B=pwg; a.C=ph; a.X=pg; a.sX=0; a.ldx=4096;
  gemm_b<E_SWIGLU,__half><<<dim3(16,8,1), 512, SMEM_B, s0>>>(a);
  cudaEventRecord(evA, s0);

  // s1: ktrans -> stage 8
  cudaStreamWaitEvent(s1, evA, 0);
  ktrans<<<dim3(8,64,16), dim3(32,8), 0, s1>>>(ph, phT);
  cudaEventRecord(evT, s1);
  {
    GArg a8; a8.pvec = alpha; a8.rvec = nullptr; a8.rout = nullptr;
    a8.X = nullptr; a8.sX = 0; a8.ldx = 0;
    a8.A=padjh; a8.sA=(long long)2048*2048; a8.lda=2048;
    a8.B=phT;   a8.sB=(long long)256*2048;  a8.ldb=2048;
    a8.C=pcb+256; a8.sC=(long long)2048*1024; a8.ldc=1024; a8.K=2048;
    gemm_b<E_SCALEH,__half><<<dim3(1,8,16), 512, SMEM_B, s1>>>(a8);
  }
  cudaEventRecord(ev8, s1);

  // s2: stage 4 (K proj) -> kcomb
  cudaStreamWaitEvent(s2, evA, 0);
  {
    GArg a4; a4.pvec = nullptr; a4.rvec = nullptr; a4.rout = nullptr;
    a4.X = nullptr; a4.sX = 0; a4.ldx = 0;
    a4.A=ph; a4.sA=256; a4.lda=4096; a4.B=pwk; a4.sB=65536; a4.ldb=256;
    a4.C=pk; a4.sC=(long long)2048*256; a4.ldc=256; a4.K=256;
    gemm_b<E_RAW,__half><<<dim3(1,8,16), 512, SMEM_B, s2>>>(a4);
  }
  cudaEventRecord(ev4, s2);
  kcomb<<<32768, 256, 0, s2>>>(ph, pcb, eps);
  cudaEventRecord(evC, s2);

  // s0: 3) Q proj
  cudaStreamWaitEvent(s0, evW, 0);
  a.A=ph; a.sA=256; a.lda=4096; a.B=pwq; a.sB=65536; a.ldb=256;
  a.C=pq; a.sC=(long long)2048*256; a.ldc=256; a.K=256; a.X=nullptr;
  gemm_b<E_RAW,__half><<<dim3(1,8,16), 512, SMEM_B, s0>>>(a);

  // s0: 5) P_unnorm + fused row sums
  cudaStreamWaitEvent(s0, ev4, 0);
  cudaStreamWaitEvent(s0, evH, 0);
  a.A=pq; a.sA=(long long)2048*256; a.lda=256;
  a.B=pk; a.sB=(long long)2048*256; a.ldb=256;
  a.C=pph; a.sC=(long long)2048*2048; a.ldc=2048; a.K=256;
  a.X=padjh; a.sX=(long long)2048*2048; a.ldx=2048;
  a.rout=prs;
  gemm_b<E_PEXP,__half><<<dim3(8,8,16), 512, SMEM_B, s0>>>(a);
  a.rout=nullptr;

  // s0: 9) attn_agg
  cudaStreamWaitEvent(s0, evT, 0);
  a.A=pph; a.sA=(long long)2048*2048; a.lda=2048;
  a.B=phT; a.sB=(long long)256*2048;  a.ldb=2048;
  a.C=pcb+768; a.sC=(long long)2048*1024; a.ldc=1024; a.K=2048;
  a.X=nullptr; a.rvec=prs;
  gemm_b<E_RSCALE,__half><<<dim3(1,8,16), 512, SMEM_B, s0>>>(a);
  a.rvec=nullptr;

  // join
  cudaStreamWaitEvent(s0, ev8, 0);
  cudaStreamWaitEvent(s0, evC, 0);

  // s0: 10) t = silu(comb @ W1^T)
  a.A=pcb; a.sA=(long long)2048*1024; a.lda=1024;
  a.B=pw1; a.sB=0; a.ldb=1024;
  a.C=pt;  a.sC=(long long)2048*256; a.ldc=256; a.K=1024;
  gemm_b<E_SILU,__half><<<dim3(1,8,16), 512, SMEM_B, s0>>>(a);

  // s0: 11) gin = t @ W2^T
  a.A=pt; a.sA=(long long)2048*256; a.lda=256;
  a.B=pw2; a.sB=0; a.ldb=256;
  a.C=pg; a.sC=256; a.ldc=4096; a.K=256;
  gemm_b<E_RAW,__half><<<dim3(1,8,16), 512, SMEM_B, s0>>>(a);

  // s0: 12) out = gin @ Wd^T (128x128 tiles: N=1024 would underfill big grid)
  a.A=pg;  a.sA=0; a.lda=4096;
  a.B=pwd; a.sB=0; a.ldb=4096;
  a.C=out; a.sC=0; a.ldc=1024; a.K=4096;
  gemm_h<E_RAW,float><<<dim3(8,16,1), 256, SMEM_S, s0>>>(a);
}

// round 15
// speedup vs baseline: 1.8175x; 1.8175x over previous
#include <cuda_runtime.h>
#include <cuda_fp16.h>
#include <cstdint>

#define DI __device__ __forceinline__

constexpr int SEQ = 2048, HIDN = 1024, NHD = 16, ITR = 4096, HD = 256;

// ---------------- scratch (device globals; allocation-free) ----------------
__device__ __align__(16) __half g_xh [SEQ * HIDN];
__device__ __align__(16) __half g_wg [ITR * HIDN];
__device__ __align__(16) __half g_wu [ITR * HIDN];
__device__ __align__(16) __half g_wd [HIDN * ITR];
__device__ __align__(16) __half g_wq [NHD * HD * HD];
__device__ __align__(16) __half g_wk [NHD * HD * HD];
__device__ __align__(16) __half g_w1 [HD * 4 * HD];
__device__ __align__(16) __half g_w2t[HD * HD];                   // W2^T (d,e)
__device__ __align__(16) __half g_fw [HIDN * ITR];                // fused Wd_h@W2, (j, h*256+e)
__device__ __align__(16) __half g_adjh[(size_t)NHD * SEQ * SEQ];
__device__ __align__(16) __half g_h  [SEQ * ITR];
__device__ __align__(16) __half g_hT [NHD * HD * SEQ];
__device__ __align__(16) __half g_q  [NHD * SEQ * HD];
__device__ __align__(16) __half g_k2 [NHD * SEQ * HD];
__device__ __align__(16) __half g_ph [(size_t)NHD * SEQ * SEQ];
__device__ float                g_rs [NHD * SEQ];
__device__ __align__(16) __half g_cb [(size_t)NHD * SEQ * 4 * HD];
__device__ __align__(16) __half g_gin[SEQ * ITR];                 // U scratch, then tI

// ---------------- MUFU-free math ----------------
DI float exp_nm(float x){
  float t = fminf(fmaxf(x * 1.44269504f, -126.f), 126.f);
  float n = rintf(t);
  float y = (t - n) * 0.693147181f;
  float p = 1.f + y*(1.f + y*(0.5f + y*(0.166666667f + y*(0.0416666667f +
            y*(0.00833333333f + y*0.00138888889f)))));
  return p * __int_as_float(((int)n + 127) << 23);
}
DI float recip_nm(float d){
  float r = __int_as_float(0x7EF311C3u - __float_as_uint(d));
  r = r * (2.f - d*r); r = r * (2.f - d*r); r = r * (2.f - d*r);
  return r;
}
DI float silu_nm(float v){ return v * recip_nm(1.f + exp_nm(-v)); }

DI void mma16(float c[4], const uint32_t a[4], const uint32_t b[2]){
  asm volatile("mma.sync.aligned.m16n8k16.row.col.f32.f16.f16.f32 "
    "{%0,%1,%2,%3},{%4,%5,%6,%7},{%8,%9},{%0,%1,%2,%3};\n"
    : "+f"(c[0]),"+f"(c[1]),"+f"(c[2]),"+f"(c[3])
    : "r"(a[0]),"r"(a[1]),"r"(a[2]),"r"(a[3]),"r"(b[0]),"r"(b[1]));
}
DI void ldsm4(uint32_t d[4], uint32_t addr){
  asm volatile("ldmatrix.sync.aligned.m8n8.x4.shared.b16 {%0,%1,%2,%3}, [%4];"
    : "=r"(d[0]),"=r"(d[1]),"=r"(d[2]),"=r"(d[3]) : "r"(addr));
}
DI void ldsm2(uint32_t d[2], uint32_t addr){
  asm volatile("ldmatrix.sync.aligned.m8n8.x2.shared.b16 {%0,%1}, [%2];"
    : "=r"(d[0]),"=r"(d[1]) : "r"(addr));
}
DI uint32_t cvta_s(const void* p){ return (uint32_t)__cvta_generic_to_shared(p); }
DI void cpa16(uint32_t dst, const void* src){
  asm volatile("cp.async.cg.shared.global [%0], [%1], 16;" :: "r"(dst), "l"(src));
}
DI void cpa_commit(){ asm volatile("cp.async.commit_group;" ::: "memory"); }
template<int N> DI void cpa_wait(){ asm volatile("cp.async.wait_group %0;" :: "n"(N) : "memory"); }

// ---------------- batched GEMM: C = A @ B^T (champion config) ----------------
enum { E_RAW=0, E_SWIGLU=1, E_PEXP=2, E_SCALEH=3, E_SILU=4, E_RSCALE=5 };

struct GArg {
  const void* A; long long sA; int lda;
  const void* B; long long sB; int ldb;
  void*       C; long long sC; int ldc;
  const void* X; long long sX; int ldx;
  const float* pvec;
  const float* rvec;
  float*       rout;
  int K;
};

template<int EPI, typename CT>
DI void st2(const GArg& g, int b, long long rg, long long cg, float v0, float v1){
  float o0, o1;
  if (EPI == E_RAW){ o0 = v0; o1 = v1; }
  else if (EPI == E_SWIGLU){
    __half2 u = *(const __half2*)((const __half*)g.X + rg*(long long)g.ldx + cg);
    o0 = silu_nm(v0) * __half2float(u.x); o1 = silu_nm(v1) * __half2float(u.y);
  } else if (EPI == E_PEXP){
    __half2 a2 = *(const __half2*)((const __half*)g.X + (long long)b*g.sX + rg*(long long)g.ldx + cg);
    o0 = exp_nm(v0*0.0625f) * (__half2float(a2.x) + 1e-9f);
    o1 = exp_nm(v1*0.0625f) * (__half2float(a2.y) + 1e-9f);
    float s = o0 + o1;
    s += __shfl_xor_sync(0xffffffffu, s, 1);
    s += __shfl_xor_sync(0xffffffffu, s, 2);
    if ((threadIdx.x & 3) == 0) atomicAdd(g.rout + (long long)b*SEQ + rg, s);
  } else if (EPI == E_SCALEH){ float s = g.pvec[b]; o0 = v0*s; o1 = v1*s; }
  else if (EPI == E_RSCALE){
    float s = recip_nm(g.rvec[(long long)b*SEQ + rg]); o0 = v0*s; o1 = v1*s;
  } else { o0 = silu_nm(v0); o1 = silu_nm(v1); }
  CT* p = (CT*)g.C + (long long)b*g.sC + rg*(long long)g.ldc + cg;
  if constexpr (sizeof(CT) == 2) *(__half2*)p = __floats2half2_rn(o0, o1);
  else                           *(float2*)p  = make_float2(o0, o1);
}

constexpr int ROWH = 40;
constexpr int TILEH = 128 * ROWH;
constexpr int STAGEB = 2 * TILEH * 2;          // 20480
constexpr int NST = 4;
constexpr int GEMM_SMEM = NST * STAGEB;        // 81920

template<int EPI, typename CT>
__global__ void __launch_bounds__(256, 2) gemm_h(GArg g){
  extern __shared__ __half smh[];
  const int b = blockIdx.z;
  const __half* A = (const __half*)g.A + (long long)b*g.sA;
  const __half* B = (const __half*)g.B + (long long)b*g.sB;
  const int m0 = blockIdx.y * 128, n0 = blockIdx.x * 128;
  const int tid = threadIdx.x, lane = tid & 31, wid = tid >> 5;
  const int wm = wid & 1, wn = wid >> 1;
  const int ar = lane >> 2, ac = lane & 3;
  float acc[4][4][4] = {};

  const int rF = tid >> 1;
  const int cB = (tid & 1) * 32;

  const uint32_t smem0 = cvta_s(smh);
  const uint32_t aBase = smem0 + (wm*64 + (lane & 7) + ((lane >> 3) & 1)*8)*(ROWH*2)
                       + ((lane >> 4) & 1)*16;
  const uint32_t bBase = smem0 + TILEH*2 + (wn*32 + (lane & 7))*(ROWH*2)
                       + ((lane >> 3) & 1)*16;
  const int ktiles = g.K >> 5;

  auto issue = [&](int kt){
    if (kt < ktiles){
      int st = kt & (NST - 1);
      uint32_t ds = smem0 + st*STAGEB + rF*(ROWH*2) + cB;
      const char* sa = (const char*)(A + (long long)(m0 + rF)*g.lda + kt*32) + cB;
      const char* sb = (const char*)(B + (long long)(n0 + rF)*g.ldb + kt*32) + cB;
      cpa16(ds,             sa);
      cpa16(ds + 16,        sa + 16);
      cpa16(ds + TILEH*2,      sb);
      cpa16(ds + TILEH*2 + 16, sb + 16);
    }
    cpa_commit();
  };

  issue(0); issue(1); issue(2);

  for (int kt = 0; kt < ktiles; kt++){
    cpa_wait<2>();
    __syncthreads();
    issue(kt + 3);
    const uint32_t so = (uint32_t)(kt & (NST - 1)) * STAGEB;
    #pragma unroll
    for (int kk = 0; kk < 32; kk += 16){
      uint32_t af[4][4], bf[4][2];
      #pragma unroll
      for (int mt = 0; mt < 4; mt++)
        ldsm4(af[mt], aBase + so + mt*16*(ROWH*2) + kk*2);
      #pragma unroll
      for (int nt = 0; nt < 4; nt++)
        ldsm2(bf[nt], bBase + so + nt*8*(ROWH*2) + kk*2);
      #pragma unroll
      for (int mt = 0; mt < 4; mt++)
        #pragma unroll
        for (int nt = 0; nt < 4; nt++)
          mma16(acc[mt][nt], af[mt], bf[nt]);
    }
    __syncthreads();
  }

  #pragma unroll
  for (int mt = 0; mt < 4; mt++)
    #pragma unroll
    for (int nt = 0; nt < 4; nt++){
      long long rg = m0 + wm*64 + mt*16 + ar;
      long long cg = n0 + wn*32 + nt*8 + (ac << 1);
      st2<EPI, CT>(g, b, rg,   cg, acc[mt][nt][0], acc[mt][nt][1]);
      st2<EPI, CT>(g, b, rg+8, cg, acc[mt][nt][2], acc[mt][nt][3]);
    }
}

// ---------------- batched fp32 -> fp16 converters ----------------
struct CvtJob { const float* src; __half* dst; long long n8; };

DI void cvt_body(const CvtJob& j){
  long long i = (long long)blockIdx.x * 256 + threadIdx.x;
  if (i >= j.n8) return;
  float4 a = ((const float4*)j.src)[i*2], c = ((const float4*)j.src)[i*2+1];
  __half2 h0 = __floats2half2_rn(a.x,a.y), h1 = __floats2half2_rn(a.z,a.w);
  __half2 h2 = __floats2half2_rn(c.x,c.y), h3 = __floats2half2_rn(c.z,c.w);
  ((uint4*)j.dst)[i] = make_uint4(*(uint32_t*)&h0, *(uint32_t*)&h1,
                                  *(uint32_t*)&h2, *(uint32_t*)&h3);
}
__global__ void kf2h1(CvtJob j0){ cvt_body(j0); }
__global__ void kf2hN(CvtJob j0, CvtJob j1, CvtJob j2, CvtJob j3){
  CvtJob j = (blockIdx.y==0)?j0:(blockIdx.y==1)?j1:(blockIdx.y==2)?j2:j3;
  cvt_body(j);
}
__global__ void kzero(float* p, int n){
  int i = blockIdx.x * 256 + threadIdx.x;
  if (i < n) p[i] = 0.f;
}

// ---------------- W2 (fp32, [e,d]) -> W2^T (half, [d,e]) ----------------
__global__ void ktw2(const float* __restrict__ w2, __half* __restrict__ w2t){
  __shared__ float t[32][33];
  int e0 = blockIdx.y * 32, d0 = blockIdx.x * 32;
  int tx = threadIdx.x, ty = threadIdx.y;
  #pragma unroll
  for (int i = 0; i < 32; i += 8)
    t[ty+i][tx] = w2[(e0+ty+i)*256 + d0 + tx];
  __syncthreads();
  #pragma unroll
  for (int i = 0; i < 32; i += 8)
    w2t[(d0+ty+i)*256 + e0 + tx] = __float2half_rn(t[tx][ty+i]);
}

// ---------------- per-head transpose ----------------
__global__ void ktrans(const __half* __restrict__ h, __half* __restrict__ hT){
  __shared__ __half t[32][34];
  int hd = blockIdx.z;
  int s0 = blockIdx.y * 32, d0 = blockIdx.x * 32;
  int tx = threadIdx.x, ty = threadIdx.y;
  #pragma unroll
  for (int i = 0; i < 32; i += 8)
    t[ty+i][tx] = h[(long long)(s0+ty+i)*4096 + hd*256 + d0 + tx];
  __syncthreads();
  #pragma unroll
  for (int i = 0; i < 32; i += 8)
    hT[(long long)hd*(256*2048) + (long long)(d0+ty+i)*2048 + s0 + tx] = t[tx][ty+i];
}

// ---------------- fill comb slices 0 (orig) and 2 (max) ----------------
__global__ void kcomb(const __half* __restrict__ h, __half* __restrict__ comb,
                      const float* __restrict__ eps){
  long long i = (long long)blockIdx.x * 256 + threadIdx.x;
  int d = (int)(i & 255);
  long long sh = i >> 8;
  int s = (int)(sh & 2047);
  int hd = (int)(sh >> 11);
  float hv = __half2float(h[(long long)s * 4096 + hd * 256 + d]);
  long long base = (long long)hd * (2048 * 1024) + (long long)s * 1024 + d;
  comb[base]       = __float2half_rn((1.f + eps[hd]) * hv);
  comb[base + 512] = __float2half_rn(hv);
}

// ---------------- launch ----------------
extern "C" void kernel_launch(void* const* d_in, const int* in_sizes, int n_in,
                              void* d_out, int out_size){
  const float* x    = (const float*)d_in[0];
  const float* adj  = (const float*)d_in[1];
  const float* Wg   = (const float*)d_in[2];
  const float* Wu   = (const float*)d_in[3];
  const float* Wd   = (const float*)d_in[4];
  const float* eps  = (const float*)d_in[5];
  const float* alpha= (const float*)d_in[6];
  const float* Wq   = (const float*)d_in[7];
  const float* Wk   = (const float*)d_in[8];
  const float* W1   = (const float*)d_in[9];
  const float* W2   = (const float*)d_in[10];
  float* out = (float*)d_out;

  __half *pxh,*pwg,*pwu,*pwd,*pwq,*pwk,*pw1,*pw2t,*pfw,*padjh,*ph,*phT,*pq,*pk,*pph,*pcb,*pg;
  float *prs;
  cudaGetSymbolAddress((void**)&pxh,  g_xh);
  cudaGetSymbolAddress((void**)&pwg,  g_wg);
  cudaGetSymbolAddress((void**)&pwu,  g_wu);
  cudaGetSymbolAddress((void**)&pwd,  g_wd);
  cudaGetSymbolAddress((void**)&pwq,  g_wq);
  cudaGetSymbolAddress((void**)&pwk,  g_wk);
  cudaGetSymbolAddress((void**)&pw1,  g_w1);
  cudaGetSymbolAddress((void**)&pw2t, g_w2t);
  cudaGetSymbolAddress((void**)&pfw,  g_fw);
  cudaGetSymbolAddress((void**)&padjh,g_adjh);
  cudaGetSymbolAddress((void**)&ph,   g_h);
  cudaGetSymbolAddress((void**)&phT,  g_hT);
  cudaGetSymbolAddress((void**)&pq,   g_q);
  cudaGetSymbolAddress((void**)&pk,   g_k2);
  cudaGetSymbolAddress((void**)&pph,  g_ph);
  cudaGetSymbolAddress((void**)&prs,  g_rs);
  cudaGetSymbolAddress((void**)&pcb,  g_cb);
  cudaGetSymbolAddress((void**)&pg,   g_gin);

  static cudaStream_t s1 = nullptr, s2 = nullptr;
  static cudaEvent_t ev0, evA, evT, ev4, ev8, evC, evH, evW;
  static bool init_done = false;
  if (!init_done){
    cudaFuncSetAttribute(gemm_h<E_RAW,__half>,    cudaFuncAttributeMaxDynamicSharedMemorySize, GEMM_SMEM);
    cudaFuncSetAttribute(gemm_h<E_RAW,float>,     cudaFuncAttributeMaxDynamicSharedMemorySize, GEMM_SMEM);
    cudaFuncSetAttribute(gemm_h<E_SWIGLU,__half>, cudaFuncAttributeMaxDynamicSharedMemorySize, GEMM_SMEM);
    cudaFuncSetAttribute(gemm_h<E_PEXP,__half>,   cudaFuncAttributeMaxDynamicSharedMemorySize, GEMM_SMEM);
    cudaFuncSetAttribute(gemm_h<E_SCALEH,__half>, cudaFuncAttributeMaxDynamicSharedMemorySize, GEMM_SMEM);
    cudaFuncSetAttribute(gemm_h<E_RSCALE,__half>, cudaFuncAttributeMaxDynamicSharedMemorySize, GEMM_SMEM);
    cudaFuncSetAttribute(gemm_h<E_SILU,__half>,   cudaFuncAttributeMaxDynamicSharedMemorySize, GEMM_SMEM);
    cudaStreamCreateWithFlags(&s1, cudaStreamNonBlocking);
    cudaStreamCreateWithFlags(&s2, cudaStreamNonBlocking);
    cudaEventCreateWithFlags(&ev0, cudaEventDisableTiming);
    cudaEventCreateWithFlags(&evA, cudaEventDisableTiming);
    cudaEventCreateWithFlags(&evT, cudaEventDisableTiming);
    cudaEventCreateWithFlags(&ev4, cudaEventDisableTiming);
    cudaEventCreateWithFlags(&ev8, cudaEventDisableTiming);
    cudaEventCreateWithFlags(&evC, cudaEventDisableTiming);
    cudaEventCreateWithFlags(&evH, cudaEventDisableTiming);
    cudaEventCreateWithFlags(&evW, cudaEventDisableTiming);
    init_done = true;
  }
  cudaStream_t s0 = 0;
  auto J = [](const float* s, __half* d, long long n){ CvtJob j{s, d, n >> 3}; return j; };

  kzero<<<NHD*SEQ/256, 256, 0, s0>>>(prs, NHD*SEQ);
  cudaEventRecord(ev0, s0);

  // s1: adjacency -> half
  cudaStreamWaitEvent(s1, ev0, 0);
  kf2h1<<<dim3(32768,1), 256, 0, s1>>>(J(adj, padjh, (long long)NHD*SEQ*SEQ));
  cudaEventRecord(evH, s1);

  // s2: Wk ; Wq/W1/Wd batch ; W2^T ; fused G = Wd_h @ W2
  cudaStreamWaitEvent(s2, ev0, 0);
  kf2h1<<<dim3(512,1), 256, 0, s2>>>(J(Wk, pwk, (long long)NHD*HD*HD));
  {
    CvtJob jz{nullptr, nullptr, 0};
    kf2hN<<<dim3(2048,3), 256, 0, s2>>>(J(Wq, pwq, (long long)NHD*HD*HD),
                                        J(W1, pw1, (long long)HD*4*HD),
                                        J(Wd, pwd, (long long)HIDN*ITR), jz);
  }
  ktw2<<<dim3(8,8), dim3(32,8), 0, s2>>>(W2, pw2t);
  {
    GArg af; af.pvec=nullptr; af.rvec=nullptr; af.rout=nullptr;
    af.X=nullptr; af.sX=0; af.ldx=0;
    af.A=pwd;  af.sA=256; af.lda=4096;     // Wd_h rows j, K=256 cols e
    af.B=pw2t; af.sB=0;   af.ldb=256;      // W2T rows d, cols e
    af.C=pfw;  af.sC=256; af.ldc=4096;     // fused[j, h*256+d]
    af.K=256;
    gemm_h<E_RAW,__half><<<dim3(2,8,16), 256, GEMM_SMEM, s2>>>(af);
  }
  cudaEventRecord(evW, s2);

  // s0: x, Wu, Wg (needed immediately)
  {
    CvtJob jz{nullptr, nullptr, 0};
    kf2hN<<<dim3(2048,3), 256, 0, s0>>>(J(x, pxh, (long long)SEQ*HIDN),
                                        J(Wu, pwu, (long long)ITR*HIDN),
                                        J(Wg, pwg, (long long)ITR*HIDN), jz);
  }

  GArg a; a.pvec = nullptr; a.rvec = nullptr; a.rout = nullptr;
  a.X = nullptr; a.sX = 0; a.ldx = 0;

  // s0: 1) U = xh @ Wu^T -> g_gin ; 2) h = silu(xh@Wg^T)*U -> g_h
  a.A=pxh; a.sA=0; a.lda=1024; a.B=pwu; a.sB=0; a.ldb=1024;
  a.C=pg;  a.sC=0; a.ldc=4096; a.K=1024;
  gemm_h<E_RAW,__half><<<dim3(32,16,1), 256, GEMM_SMEM, s0>>>(a);
  a.B=pwg; a.C=ph; a.X=pg; a.sX=0; a.ldx=4096;
  gemm_h<E_SWIGLU,__half><<<dim3(32,16,1), 256, GEMM_SMEM, s0>>>(a);
  cudaEventRecord(evA, s0);

  // s1: ktrans -> stage 8 (adjh @ hT)
  cudaStreamWaitEvent(s1, evA, 0);
  ktrans<<<dim3(8,64,16), dim3(32,8), 0, s1>>>(ph, phT);
  cudaEventRecord(evT, s1);
  {
    GArg a8; a8.pvec = alpha; a8.rvec = nullptr; a8.rout = nullptr;
    a8.X = nullptr; a8.sX = 0; a8.ldx = 0;
    a8.A=padjh; a8.sA=(long long)2048*2048; a8.lda=2048;
    a8.B=phT;   a8.sB=(long long)256*2048;  a8.ldb=2048;
    a8.C=pcb+256; a8.sC=(long long)2048*1024; a8.ldc=1024; a8.K=2048;
    gemm_h<E_SCALEH,__half><<<dim3(2,16,16), 256, GEMM_SMEM, s1>>>(a8);
  }
  cudaEventRecord(ev8, s1);

  // s2: stage 4 (K proj) -> kcomb
  cudaStreamWaitEvent(s2, evA, 0);
  {
    GArg a4; a4.pvec = nullptr; a4.rvec = nullptr; a4.rout = nullptr;
    a4.X = nullptr; a4.sX = 0; a4.ldx = 0;
    a4.A=ph; a4.sA=256; a4.lda=4096; a4.B=pwk; a4.sB=65536; a4.ldb=256;
    a4.C=pk; a4.sC=(long long)2048*256; a4.ldc=256; a4.K=256;
    gemm_h<E_RAW,__half><<<dim3(2,16,16), 256, GEMM_SMEM, s2>>>(a4);
  }
  cudaEventRecord(ev4, s2);
  kcomb<<<32768, 256, 0, s2>>>(ph, pcb, eps);
  cudaEventRecord(evC, s2);

  // s0: 3) Q proj (needs Wq conversion from s2)
  cudaStreamWaitEvent(s0, evW, 0);
  a.A=ph; a.sA=256; a.lda=4096; a.B=pwq; a.sB=65536; a.ldb=256;
  a.C=pq; a.sC=(long long)2048*256; a.ldc=256; a.K=256; a.X=nullptr;
  gemm_h<E_RAW,__half><<<dim3(2,16,16), 256, GEMM_SMEM, s0>>>(a);

  // s0: 5) P_unnorm = exp(QK^T/16)*(adj+1e-9) -> g_ph ; fused row sums
  cudaStreamWaitEvent(s0, ev4, 0);
  cudaStreamWaitEvent(s0, evH, 0);
  a.A=pq; a.sA=(long long)2048*256; a.lda=256;
  a.B=pk; a.sB=(long long)2048*256; a.ldb=256;
  a.C=pph; a.sC=(long long)2048*2048; a.ldc=2048; a.K=256;
  a.X=padjh; a.sX=(long long)2048*2048; a.ldx=2048;
  a.rout=prs;
  gemm_h<E_PEXP,__half><<<dim3(16,16,16), 256, GEMM_SMEM, s0>>>(a);
  a.rout=nullptr;

  // s0: 9) attn_agg = (P_unnorm @ h) * rsum^-1
  cudaStreamWaitEvent(s0, evT, 0);
  a.A=pph; a.sA=(long long)2048*2048; a.lda=2048;
  a.B=phT; a.sB=(long long)256*2048;  a.ldb=2048;
  a.C=pcb+768; a.sC=(long long)2048*1024; a.ldc=1024; a.K=2048;
  a.X=nullptr; a.rvec=prs;
  gemm_h<E_RSCALE,__half><<<dim3(2,16,16), 256, GEMM_SMEM, s0>>>(a);
  a.rvec=nullptr;

  // join
  cudaStreamWaitEvent(s0, ev8, 0);
  cudaStreamWaitEvent(s0, evC, 0);

  // s0: 10) tI = silu(comb @ W1^T), written head-interleaved into g_gin
  a.A=pcb; a.sA=(long long)2048*1024; a.lda=1024;
  a.B=pw1; a.sB=0; a.ldb=1024;
  a.C=pg;  a.sC=256; a.ldc=4096; a.K=1024;
  gemm_h<E_SILU,__half><<<dim3(2,16,16), 256, GEMM_SMEM, s0>>>(a);

  // s0: 12) out = tI @ fused^T  (stage 11 folded into precomputed g_fw)
  a.A=pg;  a.sA=0; a.lda=4096;
  a.B=pfw; a.sB=0; a.ldb=4096;
  a.C=out; a.sC=0; a.ldc=1024; a.K=4096;
  gemm_h<E_RAW,float><<<dim3(8,16,1), 256, GEMM_SMEM, s0>>>(a);
}

// round 16
// speedup vs baseline: 1.8428x; 1.0139x over previous
#include <cuda_runtime.h>
#include <cuda_fp16.h>
#include <cstdint>

#define DI __device__ __forceinline__

constexpr int SEQ = 2048, HIDN = 1024, NHD = 16, ITR = 4096, HD = 256;

// ---------------- scratch (device globals; allocation-free) ----------------
__device__ __align__(16) __half g_xh [SEQ * HIDN];
__device__ __align__(16) __half g_wg [ITR * HIDN];
__device__ __align__(16) __half g_wu [ITR * HIDN];
__device__ __align__(16) __half g_wd [HIDN * ITR];
__device__ __align__(16) __half g_wq [NHD * HD * HD];
__device__ __align__(16) __half g_wk [NHD * HD * HD];
__device__ __align__(16) __half g_wqt[NHD * HD * HD];   // Wq^T per head (d,e)
__device__ __align__(16) __half g_wkt[NHD * HD * HD];   // Wk^T per head (d,e)
__device__ __align__(16) __half g_mt [NHD * HD * HD];   // MT[d'][d] = sum_e Wk[e,d']Wq[e,d]
__device__ __align__(16) __half g_w1 [HD * 4 * HD];
__device__ __align__(16) __half g_w2t[HD * HD];
__device__ __align__(16) __half g_fw [HIDN * ITR];      // fused Wd_h@W2
__device__ __align__(16) __half g_adjh[(size_t)NHD * SEQ * SEQ];
__device__ __align__(16) __half g_h  [SEQ * ITR];
__device__ __align__(16) __half g_hT [NHD * HD * SEQ];
__device__ __align__(16) __half g_q  [NHD * SEQ * HD];  // A' = h@M
__device__ __align__(16) __half g_ph [(size_t)NHD * SEQ * SEQ];
__device__ float                g_rs [NHD * SEQ];
__device__ __align__(16) __half g_sagg[NHD * SEQ * HD]; // raw adj@h
__device__ __align__(16) __half g_aagg[NHD * SEQ * HD]; // raw P@h
__device__ float                g_part[(size_t)NHD * SEQ * HD]; // fp32 partial of W1 contraction
__device__ __align__(16) __half g_gin[SEQ * ITR];       // U scratch, then tI

// ---------------- MUFU-free math ----------------
DI float exp_nm(float x){
  float t = fminf(fmaxf(x * 1.44269504f, -126.f), 126.f);
  float n = rintf(t);
  float y = (t - n) * 0.693147181f;
  float p = 1.f + y*(1.f + y*(0.5f + y*(0.166666667f + y*(0.0416666667f +
            y*(0.00833333333f + y*0.00138888889f)))));
  return p * __int_as_float(((int)n + 127) << 23);
}
DI float recip_nm(float d){
  float r = __int_as_float(0x7EF311C3u - __float_as_uint(d));
  r = r * (2.f - d*r); r = r * (2.f - d*r); r = r * (2.f - d*r);
  return r;
}
DI float silu_nm(float v){ return v * recip_nm(1.f + exp_nm(-v)); }

DI void mma16(float c[4], const uint32_t a[4], const uint32_t b[2]){
  asm volatile("mma.sync.aligned.m16n8k16.row.col.f32.f16.f16.f32 "
    "{%0,%1,%2,%3},{%4,%5,%6,%7},{%8,%9},{%0,%1,%2,%3};\n"
    : "+f"(c[0]),"+f"(c[1]),"+f"(c[2]),"+f"(c[3])
    : "r"(a[0]),"r"(a[1]),"r"(a[2]),"r"(a[3]),"r"(b[0]),"r"(b[1]));
}
DI void ldsm4(uint32_t d[4], uint32_t addr){
  asm volatile("ldmatrix.sync.aligned.m8n8.x4.shared.b16 {%0,%1,%2,%3}, [%4];"
    : "=r"(d[0]),"=r"(d[1]),"=r"(d[2]),"=r"(d[3]) : "r"(addr));
}
DI void ldsm2(uint32_t d[2], uint32_t addr){
  asm volatile("ldmatrix.sync.aligned.m8n8.x2.shared.b16 {%0,%1}, [%2];"
    : "=r"(d[0]),"=r"(d[1]) : "r"(addr));
}
DI uint32_t cvta_s(const void* p){ return (uint32_t)__cvta_generic_to_shared(p); }
DI void cpa16(uint32_t dst, const void* src){
  asm volatile("cp.async.cg.shared.global [%0], [%1], 16;" :: "r"(dst), "l"(src));
}
DI void cpa_commit(){ asm volatile("cp.async.commit_group;" ::: "memory"); }
template<int N> DI void cpa_wait(){ asm volatile("cp.async.wait_group %0;" :: "n"(N) : "memory"); }

// ---------------- batched GEMM: C = A @ B^T (champion config) ----------------
enum { E_RAW=0, E_SWIGLU=1, E_PEXP=2, E_EPS1=3, E_ACC=4, E_ACCB=5, E_FIN=6 };

struct GArg {
  const void* A; long long sA; int lda;
  const void* B; long long sB; int ldb;
  void*       C; long long sC; int ldc;
  const void* X; long long sX; int ldx;   // half (SWIGLU/PEXP) or float (ACC/ACCB/FIN)
  const float* pvec;
  const float* rvec;
  float*       rout;
  int K;
};

template<int EPI, typename CT>
DI void st2(const GArg& g, int b, long long rg, long long cg, float v0, float v1){
  float o0, o1;
  if (EPI == E_RAW){ o0 = v0; o1 = v1; }
  else if (EPI == E_SWIGLU){
    __half2 u = *(const __half2*)((const __half*)g.X + rg*(long long)g.ldx + cg);
    o0 = silu_nm(v0) * __half2float(u.x); o1 = silu_nm(v1) * __half2float(u.y);
  } else if (EPI == E_PEXP){
    __half2 a2 = *(const __half2*)((const __half*)g.X + (long long)b*g.sX + rg*(long long)g.ldx + cg);
    o0 = exp_nm(v0*0.0625f) * (__half2float(a2.x) + 1e-9f);
    o1 = exp_nm(v1*0.0625f) * (__half2float(a2.y) + 1e-9f);
    float s = o0 + o1;
    s += __shfl_xor_sync(0xffffffffu, s, 1);
    s += __shfl_xor_sync(0xffffffffu, s, 2);
    if ((threadIdx.x & 3) == 0) atomicAdd(g.rout + (long long)b*SEQ + rg, s);
  } else if (EPI == E_EPS1){
    float s = 1.f + g.pvec[b]; o0 = v0*s; o1 = v1*s;
  } else if (EPI == E_ACC){
    float2 xx = *(const float2*)((const float*)g.X + (long long)b*g.sX + rg*(long long)g.ldx + cg);
    o0 = v0 + xx.x; o1 = v1 + xx.y;
  } else if (EPI == E_ACCB){
    float s = g.pvec[b];
    float2 xx = *(const float2*)((const float*)g.X + (long long)b*g.sX + rg*(long long)g.ldx + cg);
    o0 = v0*s + xx.x; o1 = v1*s + xx.y;
  } else { // E_FIN
    float r = recip_nm(g.rvec[(long long)b*SEQ + rg]);
    float2 xx = *(const float2*)((const float*)g.X + (long long)b*g.sX + rg*(long long)g.ldx + cg);
    o0 = silu_nm(v0*r + xx.x); o1 = silu_nm(v1*r + xx.y);
  }
  CT* p = (CT*)g.C + (long long)b*g.sC + rg*(long long)g.ldc + cg;
  if constexpr (sizeof(CT) == 2) *(__half2*)p = __floats2half2_rn(o0, o1);
  else                           *(float2*)p  = make_float2(o0, o1);
}

constexpr int ROWH = 40;
constexpr int TILEH = 128 * ROWH;
constexpr int STAGEB = 2 * TILEH * 2;          // 20480
constexpr int NST = 4;
constexpr int GEMM_SMEM = NST * STAGEB;        // 81920

template<int EPI, typename CT>
__global__ void __launch_bounds__(256, 2) gemm_h(GArg g){
  extern __shared__ __half smh[];
  const int b = blockIdx.z;
  const __half* A = (const __half*)g.A + (long long)b*g.sA;
  const __half* B = (const __half*)g.B + (long long)b*g.sB;
  const int m0 = blockIdx.y * 128, n0 = blockIdx.x * 128;
  const int tid = threadIdx.x, lane = tid & 31, wid = tid >> 5;
  const int wm = wid & 1, wn = wid >> 1;
  const int ar = lane >> 2, ac = lane & 3;
  float acc[4][4][4] = {};

  const int rF = tid >> 1;
  const int cB = (tid & 1) * 32;

  const uint32_t smem0 = cvta_s(smh);
  const uint32_t aBase = smem0 + (wm*64 + (lane & 7) + ((lane >> 3) & 1)*8)*(ROWH*2)
                       + ((lane >> 4) & 1)*16;
  const uint32_t bBase = smem0 + TILEH*2 + (wn*32 + (lane & 7))*(ROWH*2)
                       + ((lane >> 3) & 1)*16;
  const int ktiles = g.K >> 5;

  auto issue = [&](int kt){
    if (kt < ktiles){
      int st = kt & (NST - 1);
      uint32_t ds = smem0 + st*STAGEB + rF*(ROWH*2) + cB;
      const char* sa = (const char*)(A + (long long)(m0 + rF)*g.lda + kt*32) + cB;
      const char* sb = (const char*)(B + (long long)(n0 + rF)*g.ldb + kt*32) + cB;
      cpa16(ds,             sa);
      cpa16(ds + 16,        sa + 16);
      cpa16(ds + TILEH*2,      sb);
      cpa16(ds + TILEH*2 + 16, sb + 16);
    }
    cpa_commit();
  };

  issue(0); issue(1); issue(2);

  for (int kt = 0; kt < ktiles; kt++){
    cpa_wait<2>();
    __syncthreads();
    issue(kt + 3);
    const uint32_t so = (uint32_t)(kt & (NST - 1)) * STAGEB;
    #pragma unroll
    for (int kk = 0; kk < 32; kk += 16){
      uint32_t af[4][4], bf[4][2];
      #pragma unroll
      for (int mt = 0; mt < 4; mt++)
        ldsm4(af[mt], aBase + so + mt*16*(ROWH*2) + kk*2);
      #pragma unroll
      for (int nt = 0; nt < 4; nt++)
        ldsm2(bf[nt], bBase + so + nt*8*(ROWH*2) + kk*2);
      #pragma unroll
      for (int mt = 0; mt < 4; mt++)
        #pragma unroll
        for (int nt = 0; nt < 4; nt++)
          mma16(acc[mt][nt], af[mt], bf[nt]);
    }
    __syncthreads();
  }

  #pragma unroll
  for (int mt = 0; mt < 4; mt++)
    #pragma unroll
    for (int nt = 0; nt < 4; nt++){
      long long rg = m0 + wm*64 + mt*16 + ar;
      long long cg = n0 + wn*32 + nt*8 + (ac << 1);
      st2<EPI, CT>(g, b, rg,   cg, acc[mt][nt][0], acc[mt][nt][1]);
      st2<EPI, CT>(g, b, rg+8, cg, acc[mt][nt][2], acc[mt][nt][3]);
    }
}

// ---------------- batched fp32 -> fp16 converters ----------------
struct CvtJob { const float* src; __half* dst; long long n8; };

DI void cvt_body(const CvtJob& j){
  long long i = (long long)blockIdx.x * 256 + threadIdx.x;
  if (i >= j.n8) return;
  float4 a = ((const float4*)j.src)[i*2], c = ((const float4*)j.src)[i*2+1];
  __half2 h0 = __floats2half2_rn(a.x,a.y), h1 = __floats2half2_rn(a.z,a.w);
  __half2 h2 = __floats2half2_rn(c.x,c.y), h3 = __floats2half2_rn(c.z,c.w);
  ((uint4*)j.dst)[i] = make_uint4(*(uint32_t*)&h0, *(uint32_t*)&h1,
                                  *(uint32_t*)&h2, *(uint32_t*)&h3);
}
__global__ void kf2h1(CvtJob j0){ cvt_body(j0); }
__global__ void kf2hN(CvtJob j0, CvtJob j1, CvtJob j2, CvtJob j3){
  CvtJob j = (blockIdx.y==0)?j0:(blockIdx.y==1)?j1:(blockIdx.y==2)?j2:j3;
  cvt_body(j);
}
__global__ void kzero(float* p, int n){
  int i = blockIdx.x * 256 + threadIdx.x;
  if (i < n) p[i] = 0.f;
}

// ---------------- W2 (fp32, [e,d]) -> W2^T (half, [d,e]) ----------------
__global__ void ktw2(const float* __restrict__ w2, __half* __restrict__ w2t){
  __shared__ float t[32][33];
  int e0 = blockIdx.y * 32, d0 = blockIdx.x * 32;
  int tx = threadIdx.x, ty = threadIdx.y;
  #pragma unroll
  for (int i = 0; i < 32; i += 8)
    t[ty+i][tx] = w2[(e0+ty+i)*256 + d0 + tx];
  __syncthreads();
  #pragma unroll
  for (int i = 0; i < 32; i += 8)
    w2t[(d0+ty+i)*256 + e0 + tx] = __float2half_rn(t[tx][ty+i]);
}

// ---------------- per-head 256x256 half transpose: (h,e,d) -> (h,d,e) ----------------
__global__ void kthh(const __half* __restrict__ in, __half* __restrict__ out){
  __shared__ __half t[32][34];
  int hd = blockIdx.z;
  int e0 = blockIdx.y * 32, d0 = blockIdx.x * 32;
  int tx = threadIdx.x, ty = threadIdx.y;
  #pragma unroll
  for (int i = 0; i < 32; i += 8)
    t[ty+i][tx] = in[(long long)hd*65536 + (e0+ty+i)*256 + d0 + tx];
  __syncthreads();
  #pragma unroll
  for (int i = 0; i < 32; i += 8)
    out[(long long)hd*65536 + (d0+ty+i)*256 + e0 + tx] = t[tx][ty+i];
}

// ---------------- per-head transpose h -> hT ----------------
__global__ void ktrans(const __half* __restrict__ h, __half* __restrict__ hT){
  __shared__ __half t[32][34];
  int hd = blockIdx.z;
  int s0 = blockIdx.y * 32, d0 = blockIdx.x * 32;
  int tx = threadIdx.x, ty = threadIdx.y;
  #pragma unroll
  for (int i = 0; i < 32; i += 8)
    t[ty+i][tx] = h[(long long)(s0+ty+i)*4096 + hd*256 + d0 + tx];
  __syncthreads();
  #pragma unroll
  for (int i = 0; i < 32; i += 8)
    hT[(long long)hd*(256*2048) + (long long)(d0+ty+i)*2048 + s0 + tx] = t[tx][ty+i];
}

// ---------------- launch ----------------
extern "C" void kernel_launch(void* const* d_in, const int* in_sizes, int n_in,
                              void* d_out, int out_size){
  const float* x    = (const float*)d_in[0];
  const float* adj  = (const float*)d_in[1];
  const float* Wg   = (const float*)d_in[2];
  const float* Wu   = (const float*)d_in[3];
  const float* Wd   = (const float*)d_in[4];
  const float* eps  = (const float*)d_in[5];
  const float* alpha= (const float*)d_in[6];
  const float* Wq   = (const float*)d_in[7];
  const float* Wk   = (const float*)d_in[8];
  const float* W1   = (const float*)d_in[9];
  const float* W2   = (const float*)d_in[10];
  float* out = (float*)d_out;

  __half *pxh,*pwg,*pwu,*pwd,*pwq,*pwk,*pwqt,*pwkt,*pmt,*pw1,*pw2t,*pfw,*padjh;
  __half *ph,*phT,*pq,*pph,*psagg,*paagg,*pg;
  float *prs,*ppart;
  cudaGetSymbolAddress((void**)&pxh,  g_xh);
  cudaGetSymbolAddress((void**)&pwg,  g_wg);
  cudaGetSymbolAddress((void**)&pwu,  g_wu);
  cudaGetSymbolAddress((void**)&pwd,  g_wd);
  cudaGetSymbolAddress((void**)&pwq,  g_wq);
  cudaGetSymbolAddress((void**)&pwk,  g_wk);
  cudaGetSymbolAddress((void**)&pwqt, g_wqt);
  cudaGetSymbolAddress((void**)&pwkt, g_wkt);
  cudaGetSymbolAddress((void**)&pmt,  g_mt);
  cudaGetSymbolAddress((void**)&pw1,  g_w1);
  cudaGetSymbolAddress((void**)&pw2t, g_w2t);
  cudaGetSymbolAddress((void**)&pfw,  g_fw);
  cudaGetSymbolAddress((void**)&padjh,g_adjh);
  cudaGetSymbolAddress((void**)&ph,   g_h);
  cudaGetSymbolAddress((void**)&phT,  g_hT);
  cudaGetSymbolAddress((void**)&pq,   g_q);
  cudaGetSymbolAddress((void**)&pph,  g_ph);
  cudaGetSymbolAddress((void**)&prs,  g_rs);
  cudaGetSymbolAddress((void**)&psagg,g_sagg);
  cudaGetSymbolAddress((void**)&paagg,g_aagg);
  cudaGetSymbolAddress((void**)&ppart,g_part);
  cudaGetSymbolAddress((void**)&pg,   g_gin);

  static cudaStream_t s1 = nullptr, s2 = nullptr;
  static cudaEvent_t ev0, evA, evT, ev8, evC2, evH, evW;
  static bool init_done = false;
  if (!init_done){
    cudaFuncSetAttribute(gemm_h<E_RAW,__half>,    cudaFuncAttributeMaxDynamicSharedMemorySize, GEMM_SMEM);
    cudaFuncSetAttribute(gemm_h<E_RAW,float>,     cudaFuncAttributeMaxDynamicSharedMemorySize, GEMM_SMEM);
    cudaFuncSetAttribute(gemm_h<E_SWIGLU,__half>, cudaFuncAttributeMaxDynamicSharedMemorySize, GEMM_SMEM);
    cudaFuncSetAttribute(gemm_h<E_PEXP,__half>,   cudaFuncAttributeMaxDynamicSharedMemorySize, GEMM_SMEM);
    cudaFuncSetAttribute(gemm_h<E_EPS1,float>,    cudaFuncAttributeMaxDynamicSharedMemorySize, GEMM_SMEM);
    cudaFuncSetAttribute(gemm_h<E_ACC,float>,     cudaFuncAttributeMaxDynamicSharedMemorySize, GEMM_SMEM);
    cudaFuncSetAttribute(gemm_h<E_ACCB,float>,    cudaFuncAttributeMaxDynamicSharedMemorySize, GEMM_SMEM);
    cudaFuncSetAttribute(gemm_h<E_FIN,__half>,    cudaFuncAttributeMaxDynamicSharedMemorySize, GEMM_SMEM);
    cudaStreamCreateWithFlags(&s1, cudaStreamNonBlocking);
    cudaStreamCreateWithFlags(&s2, cudaStreamNonBlocking);
    cudaEventCreateWithFlags(&ev0, cudaEventDisableTiming);
    cudaEventCreateWithFlags(&evA, cudaEventDisableTiming);
    cudaEventCreateWithFlags(&evT, cudaEventDisableTiming);
    cudaEventCreateWithFlags(&ev8, cudaEventDisableTiming);
    cudaEventCreateWithFlags(&evC2, cudaEventDisableTiming);
    cudaEventCreateWithFlags(&evH, cudaEventDisableTiming);
    cudaEventCreateWithFlags(&evW, cudaEventDisableTiming);
    init_done = true;
  }
  cudaStream_t s0 = 0;
  auto J = [](const float* s, __half* d, long long n){ CvtJob j{s, d, n >> 3}; return j; };

  kzero<<<NHD*SEQ/256, 256, 0, s0>>>(prs, NHD*SEQ);
  cudaEventRecord(ev0, s0);

  // s1: adjacency -> half
  cudaStreamWaitEvent(s1, ev0, 0);
  kf2h1<<<dim3(32768,1), 256, 0, s1>>>(J(adj, padjh, (long long)NHD*SEQ*SEQ));
  cudaEventRecord(evH, s1);

  // s2: weight prep: conversions, W2^T, fused fw, WqT/WkT, MT
  cudaStreamWaitEvent(s2, ev0, 0);
  kf2h1<<<dim3(512,1), 256, 0, s2>>>(J(Wk, pwk, (long long)NHD*HD*HD));
  {
    CvtJob jz{nullptr, nullptr, 0};
    kf2hN<<<dim3(2048,3), 256, 0, s2>>>(J(Wq, pwq, (long long)NHD*HD*HD),
                                        J(W1, pw1, (long long)HD*4*HD),
                                        J(Wd, pwd, (long long)HIDN*ITR), jz);
  }
  ktw2<<<dim3(8,8), dim3(32,8), 0, s2>>>(W2, pw2t);
  {
    GArg af; af.pvec=nullptr; af.rvec=nullptr; af.rout=nullptr;
    af.X=nullptr; af.sX=0; af.ldx=0;
    af.A=pwd;  af.sA=256; af.lda=4096;
    af.B=pw2t; af.sB=0;   af.ldb=256;
    af.C=pfw;  af.sC=256; af.ldc=4096;
    af.K=256;
    gemm_h<E_RAW,__half><<<dim3(2,8,16), 256, GEMM_SMEM, s2>>>(af);
  }
  kthh<<<dim3(8,8,16), dim3(32,8), 0, s2>>>(pwq, pwqt);
  kthh<<<dim3(8,8,16), dim3(32,8), 0, s2>>>(pwk, pwkt);
  {
    GArg am; am.pvec=nullptr; am.rvec=nullptr; am.rout=nullptr;
    am.X=nullptr; am.sX=0; am.ldx=0;
    am.A=pwkt; am.sA=65536; am.lda=256;   // rows d'
    am.B=pwqt; am.sB=65536; am.ldb=256;   // rows d
    am.C=pmt;  am.sC=65536; am.ldc=256;   // MT[d'][d]
    am.K=256;
    gemm_h<E_RAW,__half><<<dim3(2,2,16), 256, GEMM_SMEM, s2>>>(am);
  }
  cudaEventRecord(evW, s2);

  // s0: x, Wu, Wg conversions
  {
    CvtJob jz{nullptr, nullptr, 0};
    kf2hN<<<dim3(2048,3), 256, 0, s0>>>(J(x, pxh, (long long)SEQ*HIDN),
                                        J(Wu, pwu, (long long)ITR*HIDN),
                                        J(Wg, pwg, (long long)ITR*HIDN), jz);
  }

  GArg a; a.pvec = nullptr; a.rvec = nullptr; a.rout = nullptr;
  a.X = nullptr; a.sX = 0; a.ldx = 0;

  // s0: 1) U = xh @ Wu^T ; 2) h = silu(xh@Wg^T)*U
  a.A=pxh; a.sA=0; a.lda=1024; a.B=pwu; a.sB=0; a.ldb=1024;
  a.C=pg;  a.sC=0; a.ldc=4096; a.K=1024;
  gemm_h<E_RAW,__half><<<dim3(32,16,1), 256, GEMM_SMEM, s0>>>(a);
  a.B=pwg; a.C=ph; a.X=pg; a.sX=0; a.ldx=4096;
  gemm_h<E_SWIGLU,__half><<<dim3(32,16,1), 256, GEMM_SMEM, s0>>>(a);
  cudaEventRecord(evA, s0);

  // s2: part = (1+eps)*h@W1a^T ; part += h@W1c^T   (hidden)
  cudaStreamWaitEvent(s2, evA, 0);
  {
    GArg ap; ap.rvec=nullptr; ap.rout=nullptr;
    ap.A=ph; ap.sA=256; ap.lda=4096;
    ap.B=pw1; ap.sB=0; ap.ldb=1024;
    ap.C=ppart; ap.sC=(long long)2048*256; ap.ldc=256;
    ap.K=256; ap.pvec=eps; ap.X=nullptr; ap.sX=0; ap.ldx=0;
    gemm_h<E_EPS1,float><<<dim3(2,16,16), 256, GEMM_SMEM, s2>>>(ap);
    ap.pvec=nullptr; ap.B=pw1+512;
    ap.X=ppart; ap.sX=(long long)2048*256; ap.ldx=256;
    gemm_h<E_ACC,float><<<dim3(2,16,16), 256, GEMM_SMEM, s2>>>(ap);
  }
  cudaEventRecord(evC2, s2);

  // s1: ktrans -> stage8' (raw adj@h) -> part += alpha*(sagg@W1b^T)
  cudaStreamWaitEvent(s1, evA, 0);
  ktrans<<<dim3(8,64,16), dim3(32,8), 0, s1>>>(ph, phT);
  cudaEventRecord(evT, s1);
  {
    GArg a8; a8.pvec=nullptr; a8.rvec=nullptr; a8.rout=nullptr;
    a8.X=nullptr; a8.sX=0; a8.ldx=0;
    a8.A=padjh; a8.sA=(long long)2048*2048; a8.lda=2048;
    a8.B=phT;   a8.sB=(long long)256*2048;  a8.ldb=2048;
    a8.C=psagg; a8.sC=(long long)2048*256;  a8.ldc=256; a8.K=2048;
    gemm_h<E_RAW,__half><<<dim3(2,16,16), 256, GEMM_SMEM, s1>>>(a8);
  }
  cudaStreamWaitEvent(s1, evC2, 0);
  {
    GArg ab; ab.rvec=nullptr; ab.rout=nullptr;
    ab.A=psagg; ab.sA=(long long)2048*256; ab.lda=256;
    ab.B=pw1+256; ab.sB=0; ab.ldb=1024;
    ab.C=ppart; ab.sC=(long long)2048*256; ab.ldc=256;
    ab.K=256; ab.pvec=alpha;
    ab.X=ppart; ab.sX=(long long)2048*256; ab.ldx=256;
    gemm_h<E_ACCB,float><<<dim3(2,16,16), 256, GEMM_SMEM, s1>>>(ab);
  }
  cudaEventRecord(ev8, s1);

  // s0: A' = h @ M  (replaces Q and K projections)
  cudaStreamWaitEvent(s0, evW, 0);
  a.A=ph; a.sA=256; a.lda=4096;
  a.B=pmt; a.sB=65536; a.ldb=256;
  a.C=pq; a.sC=(long long)2048*256; a.ldc=256; a.K=256; a.X=nullptr;
  gemm_h<E_RAW,__half><<<dim3(2,16,16), 256, GEMM_SMEM, s0>>>(a);

  // s0: P_unnorm = exp((A' @ h^T)/16)*(adj+1e-9) ; fused row sums
  cudaStreamWaitEvent(s0, evH, 0);
  a.A=pq; a.sA=(long long)2048*256; a.lda=256;
  a.B=ph; a.sB=256; a.ldb=4096;
  a.C=pph; a.sC=(long long)2048*2048; a.ldc=2048; a.K=256;
  a.X=padjh; a.sX=(long long)2048*2048; a.ldx=2048;
  a.rout=prs;
  gemm_h<E_PEXP,__half><<<dim3(16,16,16), 256, GEMM_SMEM, s0>>>(a);
  a.rout=nullptr;

  // s0: raw P@h -> g_aagg
  cudaStreamWaitEvent(s0, evT, 0);
  a.A=pph; a.sA=(long long)2048*2048; a.lda=2048;
  a.B=phT; a.sB=(long long)256*2048;  a.ldb=2048;
  a.C=paagg; a.sC=(long long)2048*256; a.ldc=256; a.K=2048;
  a.X=nullptr;
  gemm_h<E_RAW,__half><<<dim3(2,16,16), 256, GEMM_SMEM, s0>>>(a);

  // s0: final: tI = silu((P@h)*rsum^-1 @ W1d^T + part), head-interleaved
  cudaStreamWaitEvent(s0, ev8, 0);
  a.A=paagg; a.sA=(long long)2048*256; a.lda=256;
  a.B=pw1+768; a.sB=0; a.ldb=1024;
  a.C=pg; a.sC=256; a.ldc=4096; a.K=256;
  a.rvec=prs; a.X=ppart; a.sX=(long long)2048*256; a.ldx=256;
  gemm_h<E_FIN,__half><<<dim3(2,16,16), 256, GEMM_SMEM, s0>>>(a);
  a.rvec=nullptr; a.X=nullptr; a.sX=0; a.ldx=0;

  // s0: out = tI @ fw^T
  a.A=pg;  a.sA=0; a.lda=4096;
  a.B=pfw; a.sB=0; a.ldb=4096;
  a.C=out; a.sC=0; a.ldc=1024; a.K=4096;
  gemm_h<E_RAW,float><<<dim3(8,16,1), 256, GEMM_SMEM, s0>>>(a);
}